// round 8
// baseline (speedup 1.0000x reference)
#include <cuda_runtime.h>
#include <cuda_bf16.h>
#include <cstdint>

#define M_TOT   8192
#define K_IN    4096
#define RANK    256
#define N_OUT   4096
#define VERA_SCALE (32.0f / 256.0f)

// rank-space intermediate t = (x @ A^T) * d_A : [M_TOT][RANK]
__device__ float g_t[(size_t)M_TOT * RANK];

// ------------- helpers -------------
__device__ __forceinline__ uint32_t smem_u32(const void* p) {
    uint32_t a;
    asm("{ .reg .u64 t; cvta.to.shared.u64 t, %1; cvt.u32.u64 %0, t; }" : "=r"(a) : "l"(p));
    return a;
}
__device__ __forceinline__ void ldsm4(uint32_t r[4], uint32_t addr) {
    asm volatile("ldmatrix.sync.aligned.m8n8.x4.shared.b16 {%0,%1,%2,%3}, [%4];"
                 : "=r"(r[0]), "=r"(r[1]), "=r"(r[2]), "=r"(r[3]) : "r"(addr));
}
__device__ __forceinline__ void mma_bf16(float c[4], const uint32_t a[4],
                                         uint32_t b0, uint32_t b1) {
    asm volatile(
        "mma.sync.aligned.m16n8k16.row.col.f32.bf16.bf16.f32 "
        "{%0,%1,%2,%3}, {%4,%5,%6,%7}, {%8,%9}, {%0,%1,%2,%3};"
        : "+f"(c[0]), "+f"(c[1]), "+f"(c[2]), "+f"(c[3])
        : "r"(a[0]), "r"(a[1]), "r"(a[2]), "r"(a[3]), "r"(b0), "r"(b1));
}
__device__ __forceinline__ uint32_t sw128(uint32_t b) {
    return b ^ ((b >> 3) & 0x70);
}
// Split a pair of fp32 into packed-bf16 hi (truncated top-16) and lo (residual).
__device__ __forceinline__ void split2(float a, float b, uint32_t& hi, uint32_t& lo) {
    uint32_t ua = __float_as_uint(a), ub = __float_as_uint(b);
    hi = __byte_perm(ua, ub, 0x7632);
    float fa = __uint_as_float(ua & 0xFFFF0000u);
    float fb = __uint_as_float(ub & 0xFFFF0000u);
    float la = a - fa, lb = b - fb;
    asm("cvt.rn.bf16x2.f32 %0, %1, %2;" : "=r"(lo) : "f"(lb), "f"(la));
}
__device__ __forceinline__ void cvt_store(char* dst, int XB, uint32_t off, float4 v) {
    uint32_t h0, l0, h1, l1;
    split2(v.x, v.y, h0, l0);
    split2(v.z, v.w, h1, l1);
    *reinterpret_cast<uint2*>(dst + off)      = make_uint2(h0, h1);
    *reinterpret_cast<uint2*>(dst + XB + off) = make_uint2(l0, l1);
}

// GEMM-NT: Out[m][n] = (sum_k X[m][k] * W[n][k]) * csc[n] * scale
// CTA tile (WARPS_M*WM) x (WARPS_N*WN), K-chunk 64, bf16x3 on mma.sync.
// Producer (LDG/cvt/STS for next chunk) interleaved at s-step granularity.
template <int WARPS_M, int WARPS_N, int WM, int WN>
__global__ __launch_bounds__(WARPS_M * WARPS_N * 32, 1)
void vera_hmma(const float* __restrict__ X, const float* __restrict__ W,
               const float* __restrict__ csc, float scale, float* __restrict__ Out,
               int Ntot, int K)
{
    constexpr int THREADS = WARPS_M * WARPS_N * 32;
    constexpr int CTA_M = WARPS_M * WM;
    constexpr int CTA_N = WARPS_N * WN;
    constexpr int MI = WM / 16;     // m16 tiles per warp
    constexpr int NP = WN / 16;     // n16 ldsm groups per warp
    constexpr int XB = CTA_M * 128; // bytes of one bf16 X tile (hi or lo)
    constexpr int WB = CTA_N * 128;
    constexpr int STAGE = 2 * XB + 2 * WB;
    constexpr int NX = 4 * CTA_M / THREADS;  // float4 X loads per thread per s-step
    constexpr int NW = 4 * CTA_N / THREADS;

    extern __shared__ char smem[];
    float* cs = reinterpret_cast<float*>(smem + 2 * STAGE);
    const uint32_t sb = smem_u32(smem);

    const int tid = threadIdx.x;
    const int wid = tid >> 5;
    const int lid = tid & 31;
    const int warp_m = wid % WARPS_M;
    const int warp_n = wid / WARPS_M;

    const int bm = blockIdx.x * CTA_M;
    const int bn = blockIdx.y * CTA_N;

    for (int i = tid; i < CTA_N; i += THREADS) cs[i] = csc[bn + i] * scale;

    // ldmatrix per-lane addressing
    const int rowA = warp_m * WM + (lid & 15);
    const uint32_t kbA = (uint32_t)((lid >> 4) * 16);
    const uint32_t xA  = (uint32_t)((rowA & 7) << 4);
    uint32_t pA[MI];
    #pragma unroll
    for (int mi = 0; mi < MI; ++mi) pA[mi] = (uint32_t)((rowA + mi * 16) * 128);
    const int rowB = warp_n * WN + ((lid >> 4) * 8 + (lid & 7));
    const uint32_t pB = (uint32_t)(rowB * 128);
    const uint32_t kbB = (uint32_t)(((lid >> 3) & 1) * 16);
    const uint32_t xB  = (uint32_t)((rowB & 7) << 4);

    float acc[MI][2 * NP][4];
    #pragma unroll
    for (int i = 0; i < MI; ++i)
        #pragma unroll
        for (int j = 0; j < 2 * NP; ++j)
            #pragma unroll
            for (int q = 0; q < 4; ++q)
                acc[i][j][q] = 0.0f;

    const int nchunks = K >> 6;
    const float* Xg = X + (size_t)bm * K;
    const float* Wg = W + (size_t)bn * K;
    const int pc4 = (tid & 15) << 2;

    // prologue: fill stage 0
    for (int i = tid; i < CTA_M * 16; i += THREADS) {
        int row = i >> 4, c4 = (i & 15) << 2;
        float4 v = *reinterpret_cast<const float4*>(Xg + (size_t)row * K + c4);
        cvt_store(smem, XB, sw128((uint32_t)(row * 128 + c4 * 2)), v);
    }
    for (int i = tid; i < CTA_N * 16; i += THREADS) {
        int row = i >> 4, c4 = (i & 15) << 2;
        float4 v = *reinterpret_cast<const float4*>(Wg + (size_t)row * K + c4);
        cvt_store(smem + 2 * XB, WB, sw128((uint32_t)(row * 128 + c4 * 2)), v);
    }
    __syncthreads();

    for (int ch = 0; ch < nchunks; ++ch) {
        const int b = ch & 1;
        const uint32_t base = sb + (uint32_t)(b * STAGE);
        char* dst = smem + (b ^ 1) * STAGE;
        const bool more = (ch + 1 < nchunks);
        const float* Xn = Xg + (ch + 1) * 64;
        const float* Wn = Wg + (ch + 1) * 64;

        #pragma unroll
        for (int s = 0; s < 4; ++s) {
            // issue next-chunk LDGs for this thread's slice of s-step group
            float4 xs[NX], ws[NW];
            int xrow[NX], wrow[NW];
            if (more) {
                #pragma unroll
                for (int j = 0; j < NX; ++j) {
                    xrow[j] = (tid + (s * NX + j) * THREADS) >> 4;
                    xs[j] = *reinterpret_cast<const float4*>(
                        Xn + (size_t)xrow[j] * K + pc4);
                }
                #pragma unroll
                for (int j = 0; j < NW; ++j) {
                    wrow[j] = (tid + (s * NW + j) * THREADS) >> 4;
                    ws[j] = *reinterpret_cast<const float4*>(
                        Wn + (size_t)wrow[j] * K + pc4);
                }
            }

            // ---- MMA s-step on stage b ----
            const uint32_t aoff = ((uint32_t)(s * 32) + kbA) ^ xA;
            const uint32_t boff = ((uint32_t)(s * 32) + kbB) ^ xB;
            uint32_t ah[MI][4], al[MI][4];
            #pragma unroll
            for (int mi = 0; mi < MI; ++mi) {
                ldsm4(ah[mi], base + pA[mi] + aoff);
                ldsm4(al[mi], base + XB + pA[mi] + aoff);
            }
            #pragma unroll
            for (int np = 0; np < NP; ++np) {
                uint32_t bh[4], bl[4];
                ldsm4(bh, base + 2 * XB + pB + (uint32_t)(np * 2048) + boff);
                ldsm4(bl, base + 2 * XB + WB + pB + (uint32_t)(np * 2048) + boff);
                #pragma unroll
                for (int mi = 0; mi < MI; ++mi) {
                    mma_bf16(acc[mi][2 * np],     ah[mi], bh[0], bh[1]);
                    mma_bf16(acc[mi][2 * np + 1], ah[mi], bh[2], bh[3]);
                }
                #pragma unroll
                for (int mi = 0; mi < MI; ++mi) {
                    mma_bf16(acc[mi][2 * np],     ah[mi], bl[0], bl[1]);
                    mma_bf16(acc[mi][2 * np + 1], ah[mi], bl[2], bl[3]);
                }
                #pragma unroll
                for (int mi = 0; mi < MI; ++mi) {
                    mma_bf16(acc[mi][2 * np],     al[mi], bh[0], bh[1]);
                    mma_bf16(acc[mi][2 * np + 1], al[mi], bh[2], bh[3]);
                }
            }

            // consume LDGs: cvt + STS into the other stage
            if (more) {
                #pragma unroll
                for (int j = 0; j < NX; ++j)
                    cvt_store(dst, XB,
                              sw128((uint32_t)(xrow[j] * 128 + pc4 * 2)), xs[j]);
                #pragma unroll
                for (int j = 0; j < NW; ++j)
                    cvt_store(dst + 2 * XB, WB,
                              sw128((uint32_t)(wrow[j] * 128 + pc4 * 2)), ws[j]);
            }
        }
        __syncthreads();
    }

    // epilogue
    const int mrow0 = bm + warp_m * WM + (lid >> 2);
    const int nc0   = warp_n * WN + (lid & 3) * 2;
    #pragma unroll
    for (int mi = 0; mi < MI; ++mi) {
        #pragma unroll
        for (int nj = 0; nj < 2 * NP; ++nj) {
            const int n = nc0 + nj * 8;
            const float s0 = cs[n], s1 = cs[n + 1];
            float2 v0, v1;
            v0.x = acc[mi][nj][0] * s0; v0.y = acc[mi][nj][1] * s1;
            v1.x = acc[mi][nj][2] * s0; v1.y = acc[mi][nj][3] * s1;
            const int m0 = mrow0 + mi * 16;
            *reinterpret_cast<float2*>(Out + (size_t)m0 * Ntot + bn + n) = v0;
            *reinterpret_cast<float2*>(Out + (size_t)(m0 + 8) * Ntot + bn + n) = v1;
        }
    }
}

extern "C" void kernel_launch(void* const* d_in, const int* in_sizes, int n_in,
                              void* d_out, int out_size)
{
    const float* x   = (const float*)d_in[0];  // [8192][4096]
    const float* A   = (const float*)d_in[1];  // [256][4096]
    const float* B   = (const float*)d_in[2];  // [4096][256]
    const float* d_A = (const float*)d_in[3];  // [256]
    const float* d_B = (const float*)d_in[4];  // [4096]
    float* out = (float*)d_out;                // [8192][4096]

    float* t = nullptr;
    cudaGetSymbolAddress((void**)&t, g_t);

    // GEMM1: CTA 128x128, 8 warps (2m x 4n), warp tile 64x32
    constexpr int SMEM1 = 2 * (2 * 128 * 128 + 2 * 128 * 128) + 512;    // 131584
    // GEMM2: CTA 128x256, 8 warps (2m x 4n), warp tile 64x64
    constexpr int SMEM2 = 2 * (2 * 128 * 128 + 2 * 256 * 128) + 1024;   // 197632

    cudaFuncSetAttribute((const void*)vera_hmma<2, 4, 64, 32>,
                         cudaFuncAttributeMaxDynamicSharedMemorySize, SMEM1);
    cudaFuncSetAttribute((const void*)vera_hmma<2, 4, 64, 64>,
                         cudaFuncAttributeMaxDynamicSharedMemorySize, SMEM2);

    // GEMM1: t = (x @ A^T) * d_A      M=8192, N=256, K=4096
    {
        dim3 grid(M_TOT / 128, RANK / 128);    // 64 x 2 = 128 CTAs
        vera_hmma<2, 4, 64, 32><<<grid, 256, SMEM1>>>(x, A, d_A, 1.0f, t, RANK, K_IN);
    }
    // GEMM2: out = (t @ B^T) * d_B * SCALE   M=8192, N=4096, K=256
    {
        dim3 grid(M_TOT / 128, N_OUT / 256);   // 64 x 16 = 1024 CTAs
        vera_hmma<2, 4, 64, 64><<<grid, 256, SMEM2>>>(t, B, d_B, VERA_SCALE, out,
                                                      N_OUT, RANK);
    }
}

// round 9
// speedup vs baseline: 1.0978x; 1.0978x over previous
#include <cuda_runtime.h>
#include <cuda_bf16.h>
#include <cstdint>

#define M_TOT   8192
#define K_IN    4096
#define RANK    256
#define N_OUT   4096
#define VERA_SCALE (32.0f / 256.0f)

// rank-space intermediate t = (x @ A^T) * d_A : [M_TOT][RANK]
__device__ float g_t[(size_t)M_TOT * RANK];
// pre-split bf16 hi/lo planes of A (256x4096) and B (4096x256), row-major
__device__ uint2 g_Ahi[(size_t)RANK * K_IN / 4];
__device__ uint2 g_Alo[(size_t)RANK * K_IN / 4];
__device__ uint2 g_Bhi[(size_t)N_OUT * RANK / 4];
__device__ uint2 g_Blo[(size_t)N_OUT * RANK / 4];

// ------------- helpers -------------
__device__ __forceinline__ uint32_t smem_u32(const void* p) {
    uint32_t a;
    asm("{ .reg .u64 t; cvta.to.shared.u64 t, %1; cvt.u32.u64 %0, t; }" : "=r"(a) : "l"(p));
    return a;
}
__device__ __forceinline__ void ldsm4(uint32_t r[4], uint32_t addr) {
    asm volatile("ldmatrix.sync.aligned.m8n8.x4.shared.b16 {%0,%1,%2,%3}, [%4];"
                 : "=r"(r[0]), "=r"(r[1]), "=r"(r[2]), "=r"(r[3]) : "r"(addr));
}
__device__ __forceinline__ void mma_bf16(float c[4], const uint32_t a[4],
                                         uint32_t b0, uint32_t b1) {
    asm volatile(
        "mma.sync.aligned.m16n8k16.row.col.f32.bf16.bf16.f32 "
        "{%0,%1,%2,%3}, {%4,%5,%6,%7}, {%8,%9}, {%0,%1,%2,%3};"
        : "+f"(c[0]), "+f"(c[1]), "+f"(c[2]), "+f"(c[3])
        : "r"(a[0]), "r"(a[1]), "r"(a[2]), "r"(a[3]), "r"(b0), "r"(b1));
}
__device__ __forceinline__ uint32_t sw128(uint32_t b) {
    return b ^ ((b >> 3) & 0x70);
}
// Split a pair of fp32 into packed-bf16 hi (truncated top-16) and lo (residual).
__device__ __forceinline__ void split2(float a, float b, uint32_t& hi, uint32_t& lo) {
    uint32_t ua = __float_as_uint(a), ub = __float_as_uint(b);
    hi = __byte_perm(ua, ub, 0x7632);
    float fa = __uint_as_float(ua & 0xFFFF0000u);
    float fb = __uint_as_float(ub & 0xFFFF0000u);
    float la = a - fa, lb = b - fb;
    asm("cvt.rn.bf16x2.f32 %0, %1, %2;" : "=r"(lo) : "f"(lb), "f"(la));
}

// one-shot pre-split of a weight matrix into planar bf16 hi/lo
__global__ void split_kernel(const float4* __restrict__ in, uint2* __restrict__ hi,
                             uint2* __restrict__ lo, int n4) {
    int i = blockIdx.x * blockDim.x + threadIdx.x;
    if (i < n4) {
        float4 v = in[i];
        uint32_t h0, l0, h1, l1;
        split2(v.x, v.y, h0, l0);
        split2(v.z, v.w, h1, l1);
        hi[i] = make_uint2(h0, h1);
        lo[i] = make_uint2(l0, l1);
    }
}

// GEMM-NT: Out[m][n] = (sum_k X[m][k] * W[n][k]) * csc[n] * scale
// X: fp32 (split on the fly). W: pre-split bf16 hi/lo planes (row-major, stride K).
// CTA 128x128, K-chunk 64, bf16x3 on mma.sync. 512 threads = 16 warps (4m x 4n),
// warp tile 32x32. Producer interleaved at s-step granularity. MMA passes are
// reordered for accumulator reuse distance 8 (hi pass / cross pass / cross pass).
__global__ __launch_bounds__(512, 1)
void vera_hmma(const float* __restrict__ X,
               const uint2* __restrict__ Whi, const uint2* __restrict__ Wlo,
               const float* __restrict__ csc, float scale, float* __restrict__ Out,
               int Ntot, int K)
{
    extern __shared__ char smem[];
    constexpr int STAGE = 65536;   // {Xhi,Xlo,Whi,Wlo} x 16KB
    float* cs = reinterpret_cast<float*>(smem + 2 * STAGE);
    const uint32_t sb = smem_u32(smem);

    const int tid = threadIdx.x;
    const int wid = tid >> 5;
    const int lid = tid & 31;
    const int warp_m = wid & 3;     // 4 warps along M
    const int warp_n = wid >> 2;    // 4 warps along N

    const int bm = blockIdx.x * 128;
    const int bn = blockIdx.y * 128;

    if (tid < 128) cs[tid] = csc[bn + tid] * scale;

    const int rowA = warp_m * 32 + (lid & 15);
    const uint32_t pA0 = (uint32_t)(rowA * 128);
    const uint32_t pA1 = pA0 + 16 * 128;
    const uint32_t kbA = (uint32_t)((lid >> 4) * 16);
    const uint32_t xA  = (uint32_t)((rowA & 7) << 4);
    const int rowB = warp_n * 32 + ((lid >> 4) * 8 + (lid & 7));
    const uint32_t pB0 = (uint32_t)(rowB * 128);
    const uint32_t kbB = (uint32_t)(((lid >> 3) & 1) * 16);
    const uint32_t xB  = (uint32_t)((rowB & 7) << 4);

    const int pc4 = (tid & 15) << 2;         // element column within 64-chunk
    const int Ku2 = K >> 2;                  // uint2 per W row

    float acc[2][4][4];
    #pragma unroll
    for (int i = 0; i < 2; ++i)
        #pragma unroll
        for (int j = 0; j < 4; ++j)
            #pragma unroll
            for (int q = 0; q < 4; ++q)
                acc[i][j][q] = 0.0f;

    const int nchunks = K >> 6;
    const float* Xg = X + (size_t)bm * K;
    const uint2* WgH = Whi + (size_t)bn * Ku2;
    const uint2* WgL = Wlo + (size_t)bn * Ku2;

    // prologue: fill stage 0
    #pragma unroll
    for (int it = 0; it < 4; ++it) {
        int idx = tid + it * 512;
        int row = idx >> 4;
        int c4 = (idx & 15) << 2;
        uint32_t off = sw128((uint32_t)(row * 128 + c4 * 2));
        float4 v = *reinterpret_cast<const float4*>(Xg + (size_t)row * K + c4);
        uint32_t h0, l0, h1, l1;
        split2(v.x, v.y, h0, l0);
        split2(v.z, v.w, h1, l1);
        *reinterpret_cast<uint2*>(smem + off)         = make_uint2(h0, h1);
        *reinterpret_cast<uint2*>(smem + 16384 + off) = make_uint2(l0, l1);
        *reinterpret_cast<uint2*>(smem + 32768 + off) = WgH[(size_t)row * Ku2 + (c4 >> 2)];
        *reinterpret_cast<uint2*>(smem + 49152 + off) = WgL[(size_t)row * Ku2 + (c4 >> 2)];
    }
    __syncthreads();

    for (int ch = 0; ch < nchunks; ++ch) {
        const int b = ch & 1;
        const uint32_t base = sb + (uint32_t)(b * STAGE);
        char* dst = smem + (b ^ 1) * STAGE;
        const bool more = (ch + 1 < nchunks);
        const float* Xn = Xg + (ch + 1) * 64;
        const uint2* WnH = WgH + (ch + 1) * 16;   // 64 elems = 16 uint2
        const uint2* WnL = WgL + (ch + 1) * 16;

        #pragma unroll
        for (int s = 0; s < 4; ++s) {
            // issue next-chunk LDGs (X fp32, W pre-split bf16)
            const int row = (tid + s * 512) >> 4;
            float4 xv;
            uint2 wh, wl;
            if (more) {
                xv = *reinterpret_cast<const float4*>(Xn + (size_t)row * K + pc4);
                wh = WnH[(size_t)row * Ku2 + (pc4 >> 2)];
                wl = WnL[(size_t)row * Ku2 + (pc4 >> 2)];
            }

            // ---- fragment loads ----
            const uint32_t aoff = ((uint32_t)(s * 32) + kbA) ^ xA;
            const uint32_t boff = ((uint32_t)(s * 32) + kbB) ^ xB;
            uint32_t ah[2][4], al[2][4], bh[2][4], bl[2][4];
            ldsm4(ah[0], base + pA0 + aoff);
            ldsm4(ah[1], base + pA1 + aoff);
            ldsm4(al[0], base + 16384 + pA0 + aoff);
            ldsm4(al[1], base + 16384 + pA1 + aoff);
            ldsm4(bh[0], base + 32768 + pB0 + boff);
            ldsm4(bh[1], base + 32768 + pB0 + 2048 + boff);
            ldsm4(bl[0], base + 49152 + pB0 + boff);
            ldsm4(bl[1], base + 49152 + pB0 + 2048 + boff);

            // ---- 3 passes of 8 independent MMAs (acc reuse distance = 8) ----
            #pragma unroll
            for (int np = 0; np < 2; ++np)
                #pragma unroll
                for (int mi = 0; mi < 2; ++mi) {
                    mma_bf16(acc[mi][2 * np],     ah[mi], bh[np][0], bh[np][1]);
                    mma_bf16(acc[mi][2 * np + 1], ah[mi], bh[np][2], bh[np][3]);
                }
            #pragma unroll
            for (int np = 0; np < 2; ++np)
                #pragma unroll
                for (int mi = 0; mi < 2; ++mi) {
                    mma_bf16(acc[mi][2 * np],     ah[mi], bl[np][0], bl[np][1]);
                    mma_bf16(acc[mi][2 * np + 1], ah[mi], bl[np][2], bl[np][3]);
                }
            #pragma unroll
            for (int np = 0; np < 2; ++np)
                #pragma unroll
                for (int mi = 0; mi < 2; ++mi) {
                    mma_bf16(acc[mi][2 * np],     al[mi], bh[np][0], bh[np][1]);
                    mma_bf16(acc[mi][2 * np + 1], al[mi], bh[np][2], bh[np][3]);
                }

            // consume LDGs: X gets split, W stored verbatim
            if (more) {
                const uint32_t off = sw128((uint32_t)(row * 128 + pc4 * 2));
                uint32_t h0, l0, h1, l1;
                split2(xv.x, xv.y, h0, l0);
                split2(xv.z, xv.w, h1, l1);
                *reinterpret_cast<uint2*>(dst + off)         = make_uint2(h0, h1);
                *reinterpret_cast<uint2*>(dst + 16384 + off) = make_uint2(l0, l1);
                *reinterpret_cast<uint2*>(dst + 32768 + off) = wh;
                *reinterpret_cast<uint2*>(dst + 49152 + off) = wl;
            }
        }
        __syncthreads();
    }

    // epilogue
    const int mrow0 = bm + warp_m * 32 + (lid >> 2);
    const int nc0   = warp_n * 32 + (lid & 3) * 2;
    #pragma unroll
    for (int mi = 0; mi < 2; ++mi) {
        #pragma unroll
        for (int nj = 0; nj < 4; ++nj) {
            const int n = nc0 + nj * 8;
            const float s0 = cs[n], s1 = cs[n + 1];
            float2 v0, v1;
            v0.x = acc[mi][nj][0] * s0; v0.y = acc[mi][nj][1] * s1;
            v1.x = acc[mi][nj][2] * s0; v1.y = acc[mi][nj][3] * s1;
            const int m0 = mrow0 + mi * 16;
            *reinterpret_cast<float2*>(Out + (size_t)m0 * Ntot + bn + n) = v0;
            *reinterpret_cast<float2*>(Out + (size_t)(m0 + 8) * Ntot + bn + n) = v1;
        }
    }
}

extern "C" void kernel_launch(void* const* d_in, const int* in_sizes, int n_in,
                              void* d_out, int out_size)
{
    const float* x   = (const float*)d_in[0];  // [8192][4096]
    const float* A   = (const float*)d_in[1];  // [256][4096]
    const float* B   = (const float*)d_in[2];  // [4096][256]
    const float* d_A = (const float*)d_in[3];  // [256]
    const float* d_B = (const float*)d_in[4];  // [4096]
    float* out = (float*)d_out;                // [8192][4096]

    float* t = nullptr;
    cudaGetSymbolAddress((void**)&t, g_t);
    uint2 *Ahi, *Alo, *Bhi, *Blo;
    cudaGetSymbolAddress((void**)&Ahi, g_Ahi);
    cudaGetSymbolAddress((void**)&Alo, g_Alo);
    cudaGetSymbolAddress((void**)&Bhi, g_Bhi);
    cudaGetSymbolAddress((void**)&Blo, g_Blo);

    constexpr int SMEM = 2 * 65536 + 512;      // 131584
    cudaFuncSetAttribute(vera_hmma, cudaFuncAttributeMaxDynamicSharedMemorySize, SMEM);

    // pre-split A and B (tiny: 4MB each)
    {
        int n4A = RANK * K_IN / 4;
        split_kernel<<<n4A / 256, 256>>>((const float4*)A, Ahi, Alo, n4A);
        int n4B = N_OUT * RANK / 4;
        split_kernel<<<n4B / 256, 256>>>((const float4*)B, Bhi, Blo, n4B);
    }
    // GEMM1: t = (x @ A^T) * d_A      M=8192, N=256, K=4096
    {
        dim3 grid(M_TOT / 128, RANK / 128);    // 64 x 2
        vera_hmma<<<grid, 512, SMEM>>>(x, Ahi, Alo, d_A, 1.0f, t, RANK, K_IN);
    }
    // GEMM2: out = (t @ B^T) * d_B * SCALE   M=8192, N=4096, K=256
    {
        dim3 grid(M_TOT / 128, N_OUT / 128);   // 64 x 32
        vera_hmma<<<grid, 512, SMEM>>>(t, Bhi, Blo, d_B, VERA_SCALE, out, N_OUT, RANK);
    }
}

// round 10
// speedup vs baseline: 1.1013x; 1.0031x over previous
#include <cuda_runtime.h>
#include <cuda_bf16.h>
#include <cstdint>

#define M_TOT   8192
#define K_IN    4096
#define RANK    256
#define N_OUT   4096
#define VERA_SCALE (32.0f / 256.0f)

// pre-split bf16 hi/lo planes (packed 2 elements per uint32, row-major)
__device__ uint32_t g_Ahi[(size_t)RANK * K_IN / 2];
__device__ uint32_t g_Alo[(size_t)RANK * K_IN / 2];
__device__ uint32_t g_Bhi[(size_t)N_OUT * RANK / 2];
__device__ uint32_t g_Blo[(size_t)N_OUT * RANK / 2];
// intermediate t = (x @ A^T) * d_A, stored pre-split
__device__ uint32_t g_thi[(size_t)M_TOT * RANK / 2];
__device__ uint32_t g_tlo[(size_t)M_TOT * RANK / 2];

// ------------- helpers -------------
__device__ __forceinline__ uint32_t smem_u32(const void* p) {
    uint32_t a;
    asm("{ .reg .u64 t; cvta.to.shared.u64 t, %1; cvt.u32.u64 %0, t; }" : "=r"(a) : "l"(p));
    return a;
}
__device__ __forceinline__ void ldsm4(uint32_t r[4], uint32_t addr) {
    asm volatile("ldmatrix.sync.aligned.m8n8.x4.shared.b16 {%0,%1,%2,%3}, [%4];"
                 : "=r"(r[0]), "=r"(r[1]), "=r"(r[2]), "=r"(r[3]) : "r"(addr));
}
__device__ __forceinline__ void mma_bf16(float c[4], const uint32_t a[4],
                                         uint32_t b0, uint32_t b1) {
    asm volatile(
        "mma.sync.aligned.m16n8k16.row.col.f32.bf16.bf16.f32 "
        "{%0,%1,%2,%3}, {%4,%5,%6,%7}, {%8,%9}, {%0,%1,%2,%3};"
        : "+f"(c[0]), "+f"(c[1]), "+f"(c[2]), "+f"(c[3])
        : "r"(a[0]), "r"(a[1]), "r"(a[2]), "r"(a[3]), "r"(b0), "r"(b1));
}
__device__ __forceinline__ uint32_t sw128(uint32_t b) {
    return b ^ ((b >> 3) & 0x70);
}
__device__ __forceinline__ void split2(float a, float b, uint32_t& hi, uint32_t& lo) {
    uint32_t ua = __float_as_uint(a), ub = __float_as_uint(b);
    hi = __byte_perm(ua, ub, 0x7632);
    float fa = __uint_as_float(ua & 0xFFFF0000u);
    float fb = __uint_as_float(ub & 0xFFFF0000u);
    float la = a - fa, lb = b - fb;
    asm("cvt.rn.bf16x2.f32 %0, %1, %2;" : "=r"(lo) : "f"(lb), "f"(la));
}
__device__ __forceinline__ void cpa16(uint32_t dst, const void* src) {
    asm volatile("cp.async.cg.shared.global [%0], [%1], 16;" :: "r"(dst), "l"(src));
}
#define CP_COMMIT() asm volatile("cp.async.commit_group;" ::: "memory")
#define CP_WAIT0()  asm volatile("cp.async.wait_group 0;" ::: "memory")

// one-shot pre-split of a weight matrix into planar packed-bf16 hi/lo
__global__ void split_kernel(const float4* __restrict__ in, uint32_t* __restrict__ hi,
                             uint32_t* __restrict__ lo, int n4) {
    int i = blockIdx.x * blockDim.x + threadIdx.x;
    if (i < n4) {
        float4 v = in[i];
        uint32_t h0, l0, h1, l1;
        split2(v.x, v.y, h0, l0);
        split2(v.z, v.w, h1, l1);
        hi[2 * i] = h0; hi[2 * i + 1] = h1;
        lo[2 * i] = l0; lo[2 * i + 1] = l1;
    }
}

// ============ GEMM1: t = (x @ A^T) * d_A, emitted as split hi/lo ============
// CTA 128x128, K=4096 in 64 chunks of 64. 512 threads = 16 warps (4m x 4n),
// warp tile 32x32. X: fp32 split on the fly (interleaved producer).
// W (=A matrix): pre-split planes via cp.async.
__global__ __launch_bounds__(512, 1)
void vera_g1(const float* __restrict__ X, const uint32_t* __restrict__ Whi,
             const uint32_t* __restrict__ Wlo, const float* __restrict__ dA,
             uint32_t* __restrict__ Thi, uint32_t* __restrict__ Tlo)
{
    extern __shared__ char smem[];
    constexpr int STAGE = 65536;   // Xhi,Xlo,Whi,Wlo x 16KB
    float* cs = reinterpret_cast<float*>(smem + 2 * STAGE);
    const uint32_t sb = smem_u32(smem);

    const int tid = threadIdx.x, wid = tid >> 5, lid = tid & 31;
    const int warp_m = wid & 3, warp_n = wid >> 2;
    const int bm = blockIdx.x * 128, bn = blockIdx.y * 128;

    if (tid < 128) cs[tid] = dA[bn + tid];

    const int rowA = warp_m * 32 + (lid & 15);
    const uint32_t pA0 = (uint32_t)(rowA * 128), pA1 = pA0 + 2048;
    const uint32_t kbA = (uint32_t)((lid >> 4) * 16);
    const uint32_t xA  = (uint32_t)((rowA & 7) << 4);
    const int rowB = warp_n * 32 + ((lid >> 4) * 8 + (lid & 7));
    const uint32_t pB0 = (uint32_t)(rowB * 128);
    const uint32_t kbB = (uint32_t)(((lid >> 3) & 1) * 16);
    const uint32_t xB  = (uint32_t)((rowB & 7) << 4);

    const int pc4 = (tid & 15) << 2;
    const int frow = tid >> 3, fc16 = tid & 7;    // cp.async mapping

    float acc[2][4][4];
    #pragma unroll
    for (int i = 0; i < 2; ++i)
        #pragma unroll
        for (int j = 0; j < 4; ++j)
            #pragma unroll
            for (int q = 0; q < 4; ++q) acc[i][j][q] = 0.0f;

    const float* Xg = X + (size_t)bm * K_IN;
    const uint32_t* WHb = Whi + (size_t)bn * (K_IN / 2);
    const uint32_t* WLb = Wlo + (size_t)bn * (K_IN / 2);

    // prologue: X register path, W cp.async
    #pragma unroll
    for (int it = 0; it < 4; ++it) {
        int idx = tid + it * 512;
        int row = idx >> 4, c4 = (idx & 15) << 2;
        float4 v = *reinterpret_cast<const float4*>(Xg + (size_t)row * K_IN + c4);
        uint32_t off = sw128((uint32_t)(row * 128 + c4 * 2));
        uint32_t h0, l0, h1, l1;
        split2(v.x, v.y, h0, l0);
        split2(v.z, v.w, h1, l1);
        *reinterpret_cast<uint2*>(smem + off)         = make_uint2(h0, h1);
        *reinterpret_cast<uint2*>(smem + 16384 + off) = make_uint2(l0, l1);
    }
    #pragma unroll
    for (int j = 0; j < 2; ++j) {
        int row = frow + j * 64;
        uint32_t off = sw128((uint32_t)(row * 128 + fc16 * 16));
        cpa16(sb + 32768 + off, WHb + (size_t)row * (K_IN / 2) + fc16 * 4);
        cpa16(sb + 49152 + off, WLb + (size_t)row * (K_IN / 2) + fc16 * 4);
    }
    CP_COMMIT(); CP_WAIT0();
    __syncthreads();

    for (int ch = 0; ch < 64; ++ch) {
        const int b = ch & 1;
        const uint32_t base = sb + (uint32_t)(b * STAGE);
        char* dst = smem + (b ^ 1) * STAGE;
        const uint32_t dstb = sb + (uint32_t)((b ^ 1) * STAGE);
        const bool more = (ch + 1 < 64);
        const float* Xn = Xg + (ch + 1) * 64;

        if (more) {
            const int col = (ch + 1) * 32 + fc16 * 4;
            #pragma unroll
            for (int j = 0; j < 2; ++j) {
                int row = frow + j * 64;
                uint32_t off = sw128((uint32_t)(row * 128 + fc16 * 16));
                cpa16(dstb + 32768 + off, WHb + (size_t)row * (K_IN / 2) + col);
                cpa16(dstb + 49152 + off, WLb + (size_t)row * (K_IN / 2) + col);
            }
            CP_COMMIT();
        }

        #pragma unroll
        for (int s = 0; s < 4; ++s) {
            const int row = (tid + s * 512) >> 4;
            float4 xv;
            if (more) xv = *reinterpret_cast<const float4*>(Xn + (size_t)row * K_IN + pc4);

            const uint32_t aoff = ((uint32_t)(s * 32) + kbA) ^ xA;
            const uint32_t boff = ((uint32_t)(s * 32) + kbB) ^ xB;
            uint32_t ah[2][4], al[2][4], bh[2][4], bl[2][4];
            ldsm4(ah[0], base + pA0 + aoff);
            ldsm4(ah[1], base + pA1 + aoff);
            ldsm4(al[0], base + 16384 + pA0 + aoff);
            ldsm4(al[1], base + 16384 + pA1 + aoff);
            ldsm4(bh[0], base + 32768 + pB0 + boff);
            ldsm4(bh[1], base + 32768 + pB0 + 2048 + boff);
            ldsm4(bl[0], base + 49152 + pB0 + boff);
            ldsm4(bl[1], base + 49152 + pB0 + 2048 + boff);

            #pragma unroll
            for (int np = 0; np < 2; ++np)
                #pragma unroll
                for (int mi = 0; mi < 2; ++mi) {
                    mma_bf16(acc[mi][2 * np],     ah[mi], bh[np][0], bh[np][1]);
                    mma_bf16(acc[mi][2 * np + 1], ah[mi], bh[np][2], bh[np][3]);
                }
            #pragma unroll
            for (int np = 0; np < 2; ++np)
                #pragma unroll
                for (int mi = 0; mi < 2; ++mi) {
                    mma_bf16(acc[mi][2 * np],     ah[mi], bl[np][0], bl[np][1]);
                    mma_bf16(acc[mi][2 * np + 1], ah[mi], bl[np][2], bl[np][3]);
                }
            #pragma unroll
            for (int np = 0; np < 2; ++np)
                #pragma unroll
                for (int mi = 0; mi < 2; ++mi) {
                    mma_bf16(acc[mi][2 * np],     al[mi], bh[np][0], bh[np][1]);
                    mma_bf16(acc[mi][2 * np + 1], al[mi], bh[np][2], bh[np][3]);
                }

            if (more) {
                uint32_t off = sw128((uint32_t)(row * 128 + pc4 * 2));
                uint32_t h0, l0, h1, l1;
                split2(xv.x, xv.y, h0, l0);
                split2(xv.z, xv.w, h1, l1);
                *reinterpret_cast<uint2*>(dst + off)         = make_uint2(h0, h1);
                *reinterpret_cast<uint2*>(dst + 16384 + off) = make_uint2(l0, l1);
            }
        }
        CP_WAIT0();
        __syncthreads();
    }

    // epilogue: scale by d_A and emit split hi/lo t
    const int mrow0 = bm + warp_m * 32 + (lid >> 2);
    const int nc0   = warp_n * 32 + (lid & 3) * 2;
    #pragma unroll
    for (int mi = 0; mi < 2; ++mi) {
        #pragma unroll
        for (int nj = 0; nj < 4; ++nj) {
            const int n = nc0 + nj * 8;
            const float s0 = cs[n], s1 = cs[n + 1];
            const int m0 = mrow0 + mi * 16;
            const size_t o0 = (size_t)m0 * (RANK / 2) + ((bn + n) >> 1);
            const size_t o1 = (size_t)(m0 + 8) * (RANK / 2) + ((bn + n) >> 1);
            uint32_t h, l;
            split2(acc[mi][nj][0] * s0, acc[mi][nj][1] * s1, h, l);
            Thi[o0] = h; Tlo[o0] = l;
            split2(acc[mi][nj][2] * s0, acc[mi][nj][3] * s1, h, l);
            Thi[o1] = h; Tlo[o1] = l;
        }
    }
}

// ============ GEMM2: out = (t @ B^T) * d_B * SCALE ============
// CTA 128x256, K=256 in 4 chunks. 512 threads = 16 warps (4m x 4n), warp tile
// 32x64. Both operands pre-split: producer is pure cp.async (no cvt, no STS).
__global__ __launch_bounds__(512, 1)
void vera_g2(const uint32_t* __restrict__ Ahi_, const uint32_t* __restrict__ Alo_,
             const uint32_t* __restrict__ Bhi_, const uint32_t* __restrict__ Blo_,
             const float* __restrict__ dB, float* __restrict__ Out)
{
    extern __shared__ char smem[];
    constexpr int AP = 16384, BP = 32768;
    constexpr int STAGE = 2 * AP + 2 * BP;   // 96KB
    float* cs = reinterpret_cast<float*>(smem + 2 * STAGE);
    const uint32_t sb = smem_u32(smem);

    const int tid = threadIdx.x, wid = tid >> 5, lid = tid & 31;
    const int warp_m = wid & 3, warp_n = wid >> 2;
    const int bm = blockIdx.x * 128, bn = blockIdx.y * 256;

    if (tid < 256) cs[tid] = dB[bn + tid] * VERA_SCALE;

    const int rowA = warp_m * 32 + (lid & 15);
    const uint32_t pA0 = (uint32_t)(rowA * 128), pA1 = pA0 + 2048;
    const uint32_t kbA = (uint32_t)((lid >> 4) * 16);
    const uint32_t xA  = (uint32_t)((rowA & 7) << 4);
    const int rowB = warp_n * 64 + ((lid >> 4) * 8 + (lid & 7));
    const uint32_t pB0 = (uint32_t)(rowB * 128);
    const uint32_t kbB = (uint32_t)(((lid >> 3) & 1) * 16);
    const uint32_t xB  = (uint32_t)((rowB & 7) << 4);

    const int frow = tid >> 3, fc16 = tid & 7;

    float acc[2][8][4];
    #pragma unroll
    for (int i = 0; i < 2; ++i)
        #pragma unroll
        for (int j = 0; j < 8; ++j)
            #pragma unroll
            for (int q = 0; q < 4; ++q) acc[i][j][q] = 0.0f;

    // async fill of one stage for K-chunk c
    auto fill = [&](uint32_t dstb, int c) {
        const int col = c * 32 + fc16 * 4;
        #pragma unroll
        for (int j = 0; j < 2; ++j) {
            int row = frow + j * 64;
            uint32_t off = sw128((uint32_t)(row * 128 + fc16 * 16));
            cpa16(dstb + off,      Ahi_ + (size_t)(bm + row) * 128 + col);
            cpa16(dstb + AP + off, Alo_ + (size_t)(bm + row) * 128 + col);
        }
        #pragma unroll
        for (int j = 0; j < 4; ++j) {
            int row = frow + j * 64;
            uint32_t off = sw128((uint32_t)(row * 128 + fc16 * 16));
            cpa16(dstb + 2 * AP + off,      Bhi_ + (size_t)(bn + row) * 128 + col);
            cpa16(dstb + 2 * AP + BP + off, Blo_ + (size_t)(bn + row) * 128 + col);
        }
    };

    fill(sb, 0);
    CP_COMMIT(); CP_WAIT0();
    __syncthreads();

    #pragma unroll
    for (int ch = 0; ch < 4; ++ch) {
        const int b = ch & 1;
        const uint32_t base = sb + (uint32_t)(b * STAGE);
        if (ch < 3) { fill(sb + (uint32_t)((b ^ 1) * STAGE), ch + 1); CP_COMMIT(); }

        #pragma unroll
        for (int s = 0; s < 4; ++s) {
            const uint32_t aoff = ((uint32_t)(s * 32) + kbA) ^ xA;
            const uint32_t boff = ((uint32_t)(s * 32) + kbB) ^ xB;
            uint32_t ah[2][4], al[2][4];
            ldsm4(ah[0], base + pA0 + aoff);
            ldsm4(ah[1], base + pA1 + aoff);
            ldsm4(al[0], base + AP + pA0 + aoff);
            ldsm4(al[1], base + AP + pA1 + aoff);

            #pragma unroll
            for (int g = 0; g < 2; ++g) {          // np pairs {0,1} and {2,3}
                uint32_t bh[2][4], bl[2][4];
                const uint32_t nb = base + 2 * AP + pB0 + boff + (uint32_t)(g * 4096);
                ldsm4(bh[0], nb);
                ldsm4(bh[1], nb + 2048);
                ldsm4(bl[0], nb + BP);
                ldsm4(bl[1], nb + BP + 2048);
                #pragma unroll
                for (int np = 0; np < 2; ++np)
                    #pragma unroll
                    for (int mi = 0; mi < 2; ++mi) {
                        const int j = (g * 2 + np) * 2;
                        mma_bf16(acc[mi][j],     ah[mi], bh[np][0], bh[np][1]);
                        mma_bf16(acc[mi][j + 1], ah[mi], bh[np][2], bh[np][3]);
                    }
                #pragma unroll
                for (int np = 0; np < 2; ++np)
                    #pragma unroll
                    for (int mi = 0; mi < 2; ++mi) {
                        const int j = (g * 2 + np) * 2;
                        mma_bf16(acc[mi][j],     ah[mi], bl[np][0], bl[np][1]);
                        mma_bf16(acc[mi][j + 1], ah[mi], bl[np][2], bl[np][3]);
                    }
                #pragma unroll
                for (int np = 0; np < 2; ++np)
                    #pragma unroll
                    for (int mi = 0; mi < 2; ++mi) {
                        const int j = (g * 2 + np) * 2;
                        mma_bf16(acc[mi][j],     al[mi], bh[np][0], bh[np][1]);
                        mma_bf16(acc[mi][j + 1], al[mi], bh[np][2], bh[np][3]);
                    }
            }
        }
        CP_WAIT0();
        __syncthreads();
    }

    // epilogue
    const int mrow0 = bm + warp_m * 32 + (lid >> 2);
    const int nc0   = warp_n * 64 + (lid & 3) * 2;
    #pragma unroll
    for (int mi = 0; mi < 2; ++mi) {
        #pragma unroll
        for (int nj = 0; nj < 8; ++nj) {
            const int n = nc0 + nj * 8;
            const float s0 = cs[n], s1 = cs[n + 1];
            float2 v0, v1;
            v0.x = acc[mi][nj][0] * s0; v0.y = acc[mi][nj][1] * s1;
            v1.x = acc[mi][nj][2] * s0; v1.y = acc[mi][nj][3] * s1;
            const int m0 = mrow0 + mi * 16;
            *reinterpret_cast<float2*>(Out + (size_t)m0 * N_OUT + bn + n) = v0;
            *reinterpret_cast<float2*>(Out + (size_t)(m0 + 8) * N_OUT + bn + n) = v1;
        }
    }
}

extern "C" void kernel_launch(void* const* d_in, const int* in_sizes, int n_in,
                              void* d_out, int out_size)
{
    const float* x   = (const float*)d_in[0];  // [8192][4096]
    const float* A   = (const float*)d_in[1];  // [256][4096]
    const float* B   = (const float*)d_in[2];  // [4096][256]
    const float* d_A = (const float*)d_in[3];  // [256]
    const float* d_B = (const float*)d_in[4];  // [4096]
    float* out = (float*)d_out;                // [8192][4096]

    uint32_t *Ahi, *Alo, *Bhi, *Blo, *thi, *tlo;
    cudaGetSymbolAddress((void**)&Ahi, g_Ahi);
    cudaGetSymbolAddress((void**)&Alo, g_Alo);
    cudaGetSymbolAddress((void**)&Bhi, g_Bhi);
    cudaGetSymbolAddress((void**)&Blo, g_Blo);
    cudaGetSymbolAddress((void**)&thi, g_thi);
    cudaGetSymbolAddress((void**)&tlo, g_tlo);

    constexpr int SMEM1 = 2 * 65536 + 512;                 // 131584
    constexpr int SMEM2 = 2 * (2 * 16384 + 2 * 32768) + 1024;  // 197632
    cudaFuncSetAttribute(vera_g1, cudaFuncAttributeMaxDynamicSharedMemorySize, SMEM1);
    cudaFuncSetAttribute(vera_g2, cudaFuncAttributeMaxDynamicSharedMemorySize, SMEM2);

    // pre-split A and B
    {
        int n4 = RANK * K_IN / 4;       // 262144
        split_kernel<<<n4 / 256, 256>>>((const float4*)A, Ahi, Alo, n4);
        int n4b = N_OUT * RANK / 4;     // 262144
        split_kernel<<<n4b / 256, 256>>>((const float4*)B, Bhi, Blo, n4b);
    }
    // GEMM1: t(split) = (x @ A^T) * d_A
    {
        dim3 grid(M_TOT / 128, RANK / 128);   // 64 x 2
        vera_g1<<<grid, 512, SMEM1>>>(x, Ahi, Alo, d_A, thi, tlo);
    }
    // GEMM2: out = (t @ B^T) * d_B * SCALE
    {
        dim3 grid(M_TOT / 128, N_OUT / 256);  // 64 x 16
        vera_g2<<<grid, 512, SMEM2>>>(thi, tlo, Bhi, Blo, d_B, out);
    }
}

// round 11
// speedup vs baseline: 1.2049x; 1.0941x over previous
#include <cuda_runtime.h>
#include <cuda_bf16.h>
#include <cstdint>

#define M_TOT   8192
#define K_IN    4096
#define RANK    256
#define N_OUT   4096
#define VERA_SCALE (32.0f / 256.0f)

// pre-split bf16 hi/lo planes (packed 2 elems per uint32, row-major)
__device__ uint32_t g_Ahi[(size_t)RANK * K_IN / 2];
__device__ uint32_t g_Alo[(size_t)RANK * K_IN / 2];
__device__ uint32_t g_Bhi[(size_t)N_OUT * RANK / 2];
__device__ uint32_t g_Blo[(size_t)N_OUT * RANK / 2];
__device__ uint32_t g_Xhi[(size_t)M_TOT * K_IN / 2];
__device__ uint32_t g_Xlo[(size_t)M_TOT * K_IN / 2];
// split-K partials for GEMM1 and the split intermediate t
__device__ float    g_p[2][(size_t)M_TOT * RANK];
__device__ uint32_t g_thi[(size_t)M_TOT * RANK / 2];
__device__ uint32_t g_tlo[(size_t)M_TOT * RANK / 2];

// ------------- helpers -------------
__device__ __forceinline__ uint32_t smem_u32(const void* p) {
    uint32_t a;
    asm("{ .reg .u64 t; cvta.to.shared.u64 t, %1; cvt.u32.u64 %0, t; }" : "=r"(a) : "l"(p));
    return a;
}
__device__ __forceinline__ void ldsm4(uint32_t r[4], uint32_t addr) {
    asm volatile("ldmatrix.sync.aligned.m8n8.x4.shared.b16 {%0,%1,%2,%3}, [%4];"
                 : "=r"(r[0]), "=r"(r[1]), "=r"(r[2]), "=r"(r[3]) : "r"(addr));
}
__device__ __forceinline__ void mma_bf16(float c[4], const uint32_t a[4],
                                         uint32_t b0, uint32_t b1) {
    asm volatile(
        "mma.sync.aligned.m16n8k16.row.col.f32.bf16.bf16.f32 "
        "{%0,%1,%2,%3}, {%4,%5,%6,%7}, {%8,%9}, {%0,%1,%2,%3};"
        : "+f"(c[0]), "+f"(c[1]), "+f"(c[2]), "+f"(c[3])
        : "r"(a[0]), "r"(a[1]), "r"(a[2]), "r"(a[3]), "r"(b0), "r"(b1));
}
__device__ __forceinline__ uint32_t sw128(uint32_t b) {
    return b ^ ((b >> 3) & 0x70);
}
__device__ __forceinline__ void split2(float a, float b, uint32_t& hi, uint32_t& lo) {
    uint32_t ua = __float_as_uint(a), ub = __float_as_uint(b);
    hi = __byte_perm(ua, ub, 0x7632);
    float fa = __uint_as_float(ua & 0xFFFF0000u);
    float fb = __uint_as_float(ub & 0xFFFF0000u);
    float la = a - fa, lb = b - fb;
    asm("cvt.rn.bf16x2.f32 %0, %1, %2;" : "=r"(lo) : "f"(lb), "f"(la));
}
__device__ __forceinline__ void cpa16(uint32_t dst, const void* src) {
    asm volatile("cp.async.cg.shared.global [%0], [%1], 16;" :: "r"(dst), "l"(src));
}
#define CP_COMMIT() asm volatile("cp.async.commit_group;" ::: "memory")
#define CP_WAIT0()  asm volatile("cp.async.wait_group 0;" ::: "memory")

// one-shot pre-split: fp32 matrix -> planar packed-bf16 hi/lo
__global__ void split_kernel(const float4* __restrict__ in, uint32_t* __restrict__ hi,
                             uint32_t* __restrict__ lo, int n4) {
    int i = blockIdx.x * blockDim.x + threadIdx.x;
    if (i < n4) {
        float4 v = in[i];
        uint32_t h0, l0, h1, l1;
        split2(v.x, v.y, h0, l0);
        split2(v.z, v.w, h1, l1);
        hi[2 * i] = h0; hi[2 * i + 1] = h1;
        lo[2 * i] = l0; lo[2 * i + 1] = l1;
    }
}

// combine split-K partials, scale by d_A, emit split hi/lo t
__global__ void combine_kernel(const float* __restrict__ p0, const float* __restrict__ p1,
                               const float* __restrict__ dA,
                               uint32_t* __restrict__ thi, uint32_t* __restrict__ tlo,
                               int n4) {
    int i = blockIdx.x * blockDim.x + threadIdx.x;
    if (i < n4) {
        float4 a = reinterpret_cast<const float4*>(p0)[i];
        float4 b = reinterpret_cast<const float4*>(p1)[i];
        int col = (i * 4) & (RANK - 1);
        float4 s = *reinterpret_cast<const float4*>(dA + col);
        uint32_t h, l;
        split2((a.x + b.x) * s.x, (a.y + b.y) * s.y, h, l);
        thi[2 * i] = h; tlo[2 * i] = l;
        split2((a.z + b.z) * s.z, (a.w + b.w) * s.w, h, l);
        thi[2 * i + 1] = h; tlo[2 * i + 1] = l;
    }
}

// ============ shared GEMM core ============
// GEMM-NT on pre-split operands: CTA 128x256, K-chunk 64, NCHUNKS chunks starting
// at u32 column koff. 512 threads = 16 warps (4m x 4n), warp tile 32x64.
// Pure cp.async producer. Epilogue templated by caller.
template <int NCHUNKS, int A_STRIDE_U32, int B_STRIDE_U32>
__device__ __forceinline__ void gemm_core(
    const uint32_t* __restrict__ Ahi_, const uint32_t* __restrict__ Alo_,
    const uint32_t* __restrict__ Bhi_, const uint32_t* __restrict__ Blo_,
    int bm, int bn, int koff_u32, char* smem, float acc[2][8][4])
{
    constexpr int AP = 16384, BP = 32768;
    constexpr int STAGE = 2 * AP + 2 * BP;   // 96KB
    const uint32_t sb = smem_u32(smem);

    const int tid = threadIdx.x, wid = tid >> 5, lid = tid & 31;
    const int warp_m = wid & 3, warp_n = wid >> 2;

    const int rowA = warp_m * 32 + (lid & 15);
    const uint32_t pA0 = (uint32_t)(rowA * 128), pA1 = pA0 + 2048;
    const uint32_t kbA = (uint32_t)((lid >> 4) * 16);
    const uint32_t xA  = (uint32_t)((rowA & 7) << 4);
    const int rowB = warp_n * 64 + ((lid >> 4) * 8 + (lid & 7));
    const uint32_t pB0 = (uint32_t)(rowB * 128);
    const uint32_t kbB = (uint32_t)(((lid >> 3) & 1) * 16);
    const uint32_t xB  = (uint32_t)((rowB & 7) << 4);

    const int frow = tid >> 3, fc16 = tid & 7;

    auto fill = [&](uint32_t dstb, int c) {
        const int col = koff_u32 + c * 32 + fc16 * 4;
        #pragma unroll
        for (int j = 0; j < 2; ++j) {
            int row = frow + j * 64;
            uint32_t off = sw128((uint32_t)(row * 128 + fc16 * 16));
            cpa16(dstb + off,      Ahi_ + (size_t)(bm + row) * A_STRIDE_U32 + col);
            cpa16(dstb + AP + off, Alo_ + (size_t)(bm + row) * A_STRIDE_U32 + col);
        }
        #pragma unroll
        for (int j = 0; j < 4; ++j) {
            int row = frow + j * 64;
            uint32_t off = sw128((uint32_t)(row * 128 + fc16 * 16));
            cpa16(dstb + 2 * AP + off,      Bhi_ + (size_t)(bn + row) * B_STRIDE_U32 + col);
            cpa16(dstb + 2 * AP + BP + off, Blo_ + (size_t)(bn + row) * B_STRIDE_U32 + col);
        }
    };

    fill(sb, 0);
    CP_COMMIT(); CP_WAIT0();
    __syncthreads();

    for (int ch = 0; ch < NCHUNKS; ++ch) {
        const int b = ch & 1;
        const uint32_t base = sb + (uint32_t)(b * STAGE);
        if (ch + 1 < NCHUNKS) { fill(sb + (uint32_t)((b ^ 1) * STAGE), ch + 1); CP_COMMIT(); }

        #pragma unroll
        for (int s = 0; s < 4; ++s) {
            const uint32_t aoff = ((uint32_t)(s * 32) + kbA) ^ xA;
            const uint32_t boff = ((uint32_t)(s * 32) + kbB) ^ xB;
            uint32_t ah[2][4], al[2][4];
            ldsm4(ah[0], base + pA0 + aoff);
            ldsm4(ah[1], base + pA1 + aoff);
            ldsm4(al[0], base + AP + pA0 + aoff);
            ldsm4(al[1], base + AP + pA1 + aoff);

            #pragma unroll
            for (int g = 0; g < 2; ++g) {
                uint32_t bh[2][4], bl[2][4];
                const uint32_t nb = base + 2 * AP + pB0 + boff + (uint32_t)(g * 4096);
                ldsm4(bh[0], nb);
                ldsm4(bh[1], nb + 2048);
                ldsm4(bl[0], nb + BP);
                ldsm4(bl[1], nb + BP + 2048);
                #pragma unroll
                for (int np = 0; np < 2; ++np)
                    #pragma unroll
                    for (int mi = 0; mi < 2; ++mi) {
                        const int j = (g * 2 + np) * 2;
                        mma_bf16(acc[mi][j],     ah[mi], bh[np][0], bh[np][1]);
                        mma_bf16(acc[mi][j + 1], ah[mi], bh[np][2], bh[np][3]);
                    }
                #pragma unroll
                for (int np = 0; np < 2; ++np)
                    #pragma unroll
                    for (int mi = 0; mi < 2; ++mi) {
                        const int j = (g * 2 + np) * 2;
                        mma_bf16(acc[mi][j],     ah[mi], bl[np][0], bl[np][1]);
                        mma_bf16(acc[mi][j + 1], ah[mi], bl[np][2], bl[np][3]);
                    }
                #pragma unroll
                for (int np = 0; np < 2; ++np)
                    #pragma unroll
                    for (int mi = 0; mi < 2; ++mi) {
                        const int j = (g * 2 + np) * 2;
                        mma_bf16(acc[mi][j],     al[mi], bh[np][0], bh[np][1]);
                        mma_bf16(acc[mi][j + 1], al[mi], bh[np][2], bh[np][3]);
                    }
            }
        }
        CP_WAIT0();
        __syncthreads();
    }
}

// GEMM1: partial[m][r] = sum_{k in split} X[m][k]*A[r][k]   (no scaling here)
__global__ __launch_bounds__(512, 1)
void vera_g1(const uint32_t* __restrict__ Xhi_, const uint32_t* __restrict__ Xlo_,
             const uint32_t* __restrict__ Ahi_, const uint32_t* __restrict__ Alo_,
             float* __restrict__ Part)
{
    extern __shared__ char smem[];
    const int bm = blockIdx.x * 128;
    const int split = blockIdx.y;
    float* Out = Part + (size_t)split * M_TOT * RANK;

    float acc[2][8][4];
    #pragma unroll
    for (int i = 0; i < 2; ++i)
        #pragma unroll
        for (int j = 0; j < 8; ++j)
            #pragma unroll
            for (int q = 0; q < 4; ++q) acc[i][j][q] = 0.0f;

    // split k: 32 chunks of 64 starting at elem split*2048 (= u32 col split*1024)
    gemm_core<32, K_IN / 2, K_IN / 2>(Xhi_, Xlo_, Ahi_, Alo_, bm, 0,
                                      split * 1024, smem, acc);

    const int tid = threadIdx.x, wid = tid >> 5, lid = tid & 31;
    const int warp_m = wid & 3, warp_n = wid >> 2;
    const int mrow0 = bm + warp_m * 32 + (lid >> 2);
    const int nc0   = warp_n * 64 + (lid & 3) * 2;
    #pragma unroll
    for (int mi = 0; mi < 2; ++mi) {
        #pragma unroll
        for (int nj = 0; nj < 8; ++nj) {
            const int n = nc0 + nj * 8;
            const int m0 = mrow0 + mi * 16;
            *reinterpret_cast<float2*>(Out + (size_t)m0 * RANK + n) =
                make_float2(acc[mi][nj][0], acc[mi][nj][1]);
            *reinterpret_cast<float2*>(Out + (size_t)(m0 + 8) * RANK + n) =
                make_float2(acc[mi][nj][2], acc[mi][nj][3]);
        }
    }
}

// GEMM2: out[m][o] = (sum_r t[m][r]*B[o][r]) * d_B[o] * SCALE
__global__ __launch_bounds__(512, 1)
void vera_g2(const uint32_t* __restrict__ Thi_, const uint32_t* __restrict__ Tlo_,
             const uint32_t* __restrict__ Bhi_, const uint32_t* __restrict__ Blo_,
             const float* __restrict__ dB, float* __restrict__ Out)
{
    extern __shared__ char smem[];
    constexpr int STAGE = 2 * 16384 + 2 * 32768;
    float* cs = reinterpret_cast<float*>(smem + 2 * STAGE);
    const int bm = blockIdx.x * 128;
    const int bn = blockIdx.y * 256;
    const int tid = threadIdx.x;

    if (tid < 256) cs[tid] = dB[bn + tid] * VERA_SCALE;

    float acc[2][8][4];
    #pragma unroll
    for (int i = 0; i < 2; ++i)
        #pragma unroll
        for (int j = 0; j < 8; ++j)
            #pragma unroll
            for (int q = 0; q < 4; ++q) acc[i][j][q] = 0.0f;

    gemm_core<4, RANK / 2, RANK / 2>(Thi_, Tlo_, Bhi_, Blo_, bm, bn, 0, smem, acc);

    const int wid = tid >> 5, lid = tid & 31;
    const int warp_m = wid & 3, warp_n = wid >> 2;
    const int mrow0 = bm + warp_m * 32 + (lid >> 2);
    const int nc0   = warp_n * 64 + (lid & 3) * 2;
    #pragma unroll
    for (int mi = 0; mi < 2; ++mi) {
        #pragma unroll
        for (int nj = 0; nj < 8; ++nj) {
            const int n = nc0 + nj * 8;
            const float s0 = cs[n], s1 = cs[n + 1];
            float2 v0, v1;
            v0.x = acc[mi][nj][0] * s0; v0.y = acc[mi][nj][1] * s1;
            v1.x = acc[mi][nj][2] * s0; v1.y = acc[mi][nj][3] * s1;
            const int m0 = mrow0 + mi * 16;
            *reinterpret_cast<float2*>(Out + (size_t)m0 * N_OUT + bn + n) = v0;
            *reinterpret_cast<float2*>(Out + (size_t)(m0 + 8) * N_OUT + bn + n) = v1;
        }
    }
}

extern "C" void kernel_launch(void* const* d_in, const int* in_sizes, int n_in,
                              void* d_out, int out_size)
{
    const float* x   = (const float*)d_in[0];  // [8192][4096]
    const float* A   = (const float*)d_in[1];  // [256][4096]
    const float* B   = (const float*)d_in[2];  // [4096][256]
    const float* d_A = (const float*)d_in[3];  // [256]
    const float* d_B = (const float*)d_in[4];  // [4096]
    float* out = (float*)d_out;                // [8192][4096]

    uint32_t *Ahi, *Alo, *Bhi, *Blo, *Xhi, *Xlo, *thi, *tlo;
    float* part;
    cudaGetSymbolAddress((void**)&Ahi, g_Ahi);
    cudaGetSymbolAddress((void**)&Alo, g_Alo);
    cudaGetSymbolAddress((void**)&Bhi, g_Bhi);
    cudaGetSymbolAddress((void**)&Blo, g_Blo);
    cudaGetSymbolAddress((void**)&Xhi, g_Xhi);
    cudaGetSymbolAddress((void**)&Xlo, g_Xlo);
    cudaGetSymbolAddress((void**)&thi, g_thi);
    cudaGetSymbolAddress((void**)&tlo, g_tlo);
    cudaGetSymbolAddress((void**)&part, g_p);

    constexpr int SMEM = 2 * (2 * 16384 + 2 * 32768) + 1024;  // 197632
    cudaFuncSetAttribute(vera_g1, cudaFuncAttributeMaxDynamicSharedMemorySize, SMEM);
    cudaFuncSetAttribute(vera_g2, cudaFuncAttributeMaxDynamicSharedMemorySize, SMEM);

    // pre-split A, B, X
    {
        int n4 = RANK * K_IN / 4;
        split_kernel<<<n4 / 256, 256>>>((const float4*)A, Ahi, Alo, n4);
        int n4b = N_OUT * RANK / 4;
        split_kernel<<<n4b / 256, 256>>>((const float4*)B, Bhi, Blo, n4b);
        int n4x = M_TOT * K_IN / 4;     // 8388608
        split_kernel<<<n4x / 256, 256>>>((const float4*)x, Xhi, Xlo, n4x);
    }
    // GEMM1 split-K=2: partials
    {
        dim3 grid(M_TOT / 128, 2);      // 128 CTAs
        vera_g1<<<grid, 512, SMEM>>>(Xhi, Xlo, Ahi, Alo, part);
    }
    // combine + d_A scale + split t
    {
        int n4 = M_TOT * RANK / 4;      // 524288
        combine_kernel<<<n4 / 256, 256>>>(part, part + (size_t)M_TOT * RANK,
                                          d_A, thi, tlo, n4);
    }
    // GEMM2
    {
        dim3 grid(M_TOT / 128, N_OUT / 256);  // 64 x 16
        vera_g2<<<grid, 512, SMEM>>>(thi, tlo, Bhi, Blo, d_B, out);
    }
}